// round 4
// baseline (speedup 1.0000x reference)
#include <cuda_runtime.h>
#include <cstdint>
#include <cstddef>

namespace {

constexpr int kB  = 4;
constexpr int kH  = 8;
constexpr int kL  = 2048;
constexpr int kR  = 8;
constexpr int kDV = 128;

constexpr int TM = 64;           // rows per CTA
constexpr int KT = 32;           // K-tile (cols per stage)
constexpr int NT = 256;          // threads per CTA
constexpr int NTILES = kL / KT;  // 64

constexpr int PSTRIDE = 36;      // p row stride (u32): banks 4*qid+tig -> conflict-free A frags
constexpr int VSTRIDE = 136;     // v row stride (u32): banks 8*tig+qid -> conflict-free B frags

typedef unsigned long long ull;

// ---------------- packed f32x2 helpers ----------------
__device__ __forceinline__ ull dup2(float x) {
    ull r; asm("mov.b64 %0, {%1,%1};" : "=l"(r) : "f"(x)); return r;
}
__device__ __forceinline__ void unpack2(ull v, float& lo, float& hi) {
    asm("mov.b64 {%0,%1}, %2;" : "=f"(lo), "=f"(hi) : "l"(v));
}
__device__ __forceinline__ ull fma2(ull a, ull b, ull c) {
    ull d; asm("fma.rn.f32x2 %0, %1, %2, %3;" : "=l"(d) : "l"(a), "l"(b), "l"(c));
    return d;
}

// ---------------- tf32 helpers (baseline sm_80+ PTX) ----------------
__device__ __forceinline__ uint32_t f2tf32(float x) {
    uint32_t r; asm("cvt.rna.tf32.f32 %0, %1;" : "=r"(r) : "f"(x)); return r;
}

__device__ __forceinline__ void mma_tf32(float d[4], const uint32_t a[4],
                                         uint32_t b0, uint32_t b1) {
    asm volatile(
        "mma.sync.aligned.m16n8k8.row.col.f32.tf32.tf32.f32 "
        "{%0,%1,%2,%3}, {%4,%5,%6,%7}, {%8,%9}, {%0,%1,%2,%3};"
        : "+f"(d[0]), "+f"(d[1]), "+f"(d[2]), "+f"(d[3])
        : "r"(a[0]), "r"(a[1]), "r"(a[2]), "r"(a[3]), "r"(b0), "r"(b1));
}

struct __align__(16) SmemLayout {
    uint32_t p[TM][PSTRIDE];    // 9.2 KB (tf32 bits, A tile)
    uint32_t v[KT][VSTRIDE];    // 17.4 KB (tf32 bits, B tile)
    float    a1t[kR][TM];       // 2 KB
    float    inv[TM];           // 256 B
};
// ~29 KB -> 2 CTAs/SM

__global__ void __launch_bounds__(NT, 2)
fra_kernel(const float* __restrict__ gv,
           const float* __restrict__ ga1,
           const float* __restrict__ ga2,
           const int*   __restrict__ gmask,
           float* __restrict__ gout,
           float* __restrict__ gattn)
{
    __shared__ SmemLayout S;

    const int h    = blockIdx.x;   // heads fastest: 8 heads share mask tile in L2
    const int tile = blockIdx.y;
    const int b    = blockIdx.z;
    const int bh   = b * kH + h;
    const int i0g  = tile * TM;
    const int t    = threadIdx.x;
    const int w    = t >> 5;
    const int l    = t & 31;

    const float* a2base = ga2 + (size_t)bh * kR * kL;    // stays in L1/L2
    const float* a1base = ga1 + ((size_t)bh * kL + i0g) * kR;
    const float* vbase  = gv  + (size_t)bh * kL * kDV;
    const int*   mbase  = gmask + ((size_t)b * kL + i0g) * kL;
    float* attnbase = gattn + ((size_t)bh * kL + i0g) * kL;
    float* outbase  = gout  + ((size_t)bh * kL + i0g) * kDV;

    // ---- load a1 tile transposed ----
    if (t < TM) {
        const float4* src = (const float4*)(a1base + (size_t)t * kR);
        float4 q0 = src[0], q1 = src[1];
        S.a1t[0][t] = q0.x; S.a1t[1][t] = q0.y;
        S.a1t[2][t] = q0.z; S.a1t[3][t] = q0.w;
        S.a1t[4][t] = q1.x; S.a1t[5][t] = q1.y;
        S.a1t[6][t] = q1.z; S.a1t[7][t] = q1.w;
    }
    __syncthreads();

    // ================= Phase 1: rowsum of exp(masked scores) =================
    // 4 threads per row, each scans 512 cols. a2 loads are warp-broadcast
    // (address independent of row) -> L1-resident 64KB slab.
    {
        const int i = t >> 2;
        const int q = t & 3;
        const int jstart = q * (kL / 4);
        ull a1d[kR];
        #pragma unroll
        for (int r = 0; r < kR; ++r) a1d[r] = dup2(S.a1t[r][i]);

        const int* mrow = mbase + (size_t)i * kL + jstart;
        const float* a2r0 = a2base + jstart;

        float s0 = 0.f, s1 = 0.f, s2 = 0.f, s3 = 0.f;
        #pragma unroll 2
        for (int j = 0; j < kL / 4; j += 4) {
            int4 m = *(const int4*)(mrow + j);
            ull a01 = 0ULL, a23 = 0ULL;
            #pragma unroll
            for (int r = 0; r < kR; ++r) {
                ulonglong2 qv = *(const ulonglong2*)(a2r0 + (size_t)r * kL + j);
                a01 = fma2(a1d[r], qv.x, a01);
                a23 = fma2(a1d[r], qv.y, a23);
            }
            float e0, e1, e2, e3;
            unpack2(a01, e0, e1);
            unpack2(a23, e2, e3);
            s0 += __expf(e0) * (float)m.x;
            s1 += __expf(e1) * (float)m.y;
            s2 += __expf(e2) * (float)m.z;
            s3 += __expf(e3) * (float)m.w;
        }
        float sum = (s0 + s1) + (s2 + s3);
        sum += __shfl_xor_sync(0xffffffffu, sum, 1);
        sum += __shfl_xor_sync(0xffffffffu, sum, 2);
        if (q == 0) S.inv[i] = 1.0f / sum;
    }
    __syncthreads();

    // ================= Phase 2: probs (fp32-exact attn) + HMMA tf32 PV GEMM =================
    // score mapping: 2 rows x 4 cols per thread
    const int rp = t >> 3;            // rows 2*rp, 2*rp+1
    const int cg = t & 7;             // cols 4*cg within K-tile
    // GEMM: 8 warps as 2x4; warp tile 32 rows x 32 cols
    const int wm  = w >> 2;
    const int wn  = w & 3;
    const int qid = l >> 2;
    const int tig = l & 3;

    float a1r[2][kR], invr[2];
    #pragma unroll
    for (int i = 0; i < 2; ++i) {
        #pragma unroll
        for (int r = 0; r < kR; ++r) a1r[i][r] = S.a1t[r][rp * 2 + i];
        invr[i] = S.inv[rp * 2 + i];
    }

    float acc[2][4][4];
    #pragma unroll
    for (int mt = 0; mt < 2; ++mt)
        #pragma unroll
        for (int nt = 0; nt < 4; ++nt)
            #pragma unroll
            for (int e = 0; e < 4; ++e) acc[mt][nt][e] = 0.f;

    for (int jt = 0; jt < NTILES; ++jt) {
        const int j0 = jt * KT;

        // ---- stage v tile -> tf32 smem (coalesced rows, conflict-free B layout) ----
        #pragma unroll
        for (int k = 0; k < 4; ++k) {
            const int row = w + 8 * k;
            float4 q = *(const float4*)(vbase + (size_t)(j0 + row) * kDV + 4 * l);
            uint4 u;
            u.x = f2tf32(q.x); u.y = f2tf32(q.y);
            u.z = f2tf32(q.z); u.w = f2tf32(q.w);
            *(uint4*)&S.v[row][4 * l] = u;
        }

        // ---- scores for 2 rows x 4 cols; exp, normalize, mask; attn STG + p STS ----
        {
            ull sac[2][2];
            sac[0][0] = 0ULL; sac[0][1] = 0ULL;
            sac[1][0] = 0ULL; sac[1][1] = 0ULL;
            #pragma unroll
            for (int r = 0; r < kR; ++r) {
                ulonglong2 q = *(const ulonglong2*)(a2base + (size_t)r * kL + j0 + cg * 4);
                #pragma unroll
                for (int i = 0; i < 2; ++i) {
                    ull ad = dup2(a1r[i][r]);
                    sac[i][0] = fma2(ad, q.x, sac[i][0]);
                    sac[i][1] = fma2(ad, q.y, sac[i][1]);
                }
            }
            #pragma unroll
            for (int i = 0; i < 2; ++i) {
                const int row = rp * 2 + i;
                int4 m = *(const int4*)(mbase + (size_t)row * kL + j0 + cg * 4);
                float e0, e1, e2, e3;
                unpack2(sac[i][0], e0, e1);
                unpack2(sac[i][1], e2, e3);
                float4 p;
                p.x = m.x ? __expf(e0) * invr[i] : 0.f;
                p.y = m.y ? __expf(e1) * invr[i] : 0.f;
                p.z = m.z ? __expf(e2) * invr[i] : 0.f;
                p.w = m.w ? __expf(e3) * invr[i] : 0.f;
                *(float4*)(attnbase + (size_t)row * kL + j0 + cg * 4) = p;
                uint4 u;
                u.x = f2tf32(p.x); u.y = f2tf32(p.y);
                u.z = f2tf32(p.z); u.w = f2tf32(p.w);
                *(uint4*)&S.p[row][cg * 4] = u;
            }
        }

        __syncthreads();

        // ---- HMMA: D[32*wm.., 32*wn..] += P * V ----
        #pragma unroll
        for (int s = 0; s < 4; ++s) {
            const int k0 = 8 * s + tig;
            uint32_t a[2][4];
            #pragma unroll
            for (int mt = 0; mt < 2; ++mt) {
                const uint32_t* pr = &S.p[32 * wm + 16 * mt][0];
                a[mt][0] = pr[(size_t)qid * PSTRIDE + k0];
                a[mt][1] = pr[(size_t)(qid + 8) * PSTRIDE + k0];
                a[mt][2] = pr[(size_t)qid * PSTRIDE + k0 + 4];
                a[mt][3] = pr[(size_t)(qid + 8) * PSTRIDE + k0 + 4];
            }
            #pragma unroll
            for (int nt = 0; nt < 4; ++nt) {
                const int n = 32 * wn + 8 * nt + qid;
                uint32_t b0 = S.v[8 * s + tig][n];
                uint32_t b1 = S.v[8 * s + 4 + tig][n];
                mma_tf32(acc[0][nt], a[0], b0, b1);
                mma_tf32(acc[1][nt], a[1], b0, b1);
            }
        }

        __syncthreads();
    }

    // ---- epilogue: D fragments -> gout ----
    #pragma unroll
    for (int mt = 0; mt < 2; ++mt) {
        #pragma unroll
        for (int nt = 0; nt < 4; ++nt) {
            const int row = 32 * wm + 16 * mt + qid;
            const int col = 32 * wn + 8 * nt + 2 * tig;
            float2 lo; lo.x = acc[mt][nt][0]; lo.y = acc[mt][nt][1];
            float2 hi; hi.x = acc[mt][nt][2]; hi.y = acc[mt][nt][3];
            *(float2*)(outbase + (size_t)row * kDV + col)       = lo;
            *(float2*)(outbase + (size_t)(row + 8) * kDV + col) = hi;
        }
    }
}

} // namespace

extern "C" void kernel_launch(void* const* d_in, const int* in_sizes, int n_in,
                              void* d_out, int out_size) {
    const float* v    = (const float*)d_in[0];
    const float* a1   = (const float*)d_in[1];
    const float* a2   = (const float*)d_in[2];
    const int*   mask = (const int*)d_in[3];

    float* out  = (float*)d_out;
    float* attn = out + (size_t)kB * kH * kL * kDV;

    dim3 grid(kH, kL / TM, kB);   // heads fastest -> mask tile L2 reuse across 8 heads
    fra_kernel<<<grid, NT>>>(v, a1, a2, mask, out, attn);
}